// round 1
// baseline (speedup 1.0000x reference)
#include <cuda_runtime.h>
#include <cuda_bf16.h>

// Scalar reduction: mean over all elements of
//   term = (a<0 && b<0) ? (b - 2a)^2 : b^2
// where a = target (d_in[1]), b = source (d_in[0]).
// Derivation: fdback - a = (a<0&&b<0) ? (b-a)-a = b-2a : (a-b)-a = -b.

__device__ double g_fdloss_sum;

__global__ void fdloss_zero_kernel() {
    g_fdloss_sum = 0.0;
}

__global__ __launch_bounds__(256) void fdloss_reduce_kernel(
    const float4* __restrict__ src,   // b
    const float4* __restrict__ tgt,   // a
    long long n4)
{
    const long long stride = (long long)gridDim.x * blockDim.x;
    long long i = (long long)blockIdx.x * blockDim.x + threadIdx.x;

    double acc = 0.0;

    // 2-way ILP over float4 pairs for deeper MLP
    for (; i + stride < n4; i += 2 * stride) {
        float4 b0 = src[i];
        float4 a0 = tgt[i];
        float4 b1 = src[i + stride];
        float4 a1 = tgt[i + stride];

        float s0, s1;
        {
            float t;
            t = (a0.x < 0.f && b0.x < 0.f) ? (b0.x - 2.f * a0.x) : b0.x;
            s0 = t * t;
            t = (a0.y < 0.f && b0.y < 0.f) ? (b0.y - 2.f * a0.y) : b0.y;
            s0 += t * t;
            t = (a0.z < 0.f && b0.z < 0.f) ? (b0.z - 2.f * a0.z) : b0.z;
            s0 += t * t;
            t = (a0.w < 0.f && b0.w < 0.f) ? (b0.w - 2.f * a0.w) : b0.w;
            s0 += t * t;
        }
        {
            float t;
            t = (a1.x < 0.f && b1.x < 0.f) ? (b1.x - 2.f * a1.x) : b1.x;
            s1 = t * t;
            t = (a1.y < 0.f && b1.y < 0.f) ? (b1.y - 2.f * a1.y) : b1.y;
            s1 += t * t;
            t = (a1.z < 0.f && b1.z < 0.f) ? (b1.z - 2.f * a1.z) : b1.z;
            s1 += t * t;
            t = (a1.w < 0.f && b1.w < 0.f) ? (b1.w - 2.f * a1.w) : b1.w;
            s1 += t * t;
        }
        acc += (double)s0 + (double)s1;
    }
    // tail (at most one float4 per thread)
    if (i < n4) {
        float4 b0 = src[i];
        float4 a0 = tgt[i];
        float t, s0;
        t = (a0.x < 0.f && b0.x < 0.f) ? (b0.x - 2.f * a0.x) : b0.x;
        s0 = t * t;
        t = (a0.y < 0.f && b0.y < 0.f) ? (b0.y - 2.f * a0.y) : b0.y;
        s0 += t * t;
        t = (a0.z < 0.f && b0.z < 0.f) ? (b0.z - 2.f * a0.z) : b0.z;
        s0 += t * t;
        t = (a0.w < 0.f && b0.w < 0.f) ? (b0.w - 2.f * a0.w) : b0.w;
        s0 += t * t;
        acc += (double)s0;
    }

    // warp reduce (double)
    #pragma unroll
    for (int off = 16; off > 0; off >>= 1)
        acc += __shfl_down_sync(0xFFFFFFFFu, acc, off);

    __shared__ double warp_sums[8];  // 256 threads = 8 warps
    const int lane = threadIdx.x & 31;
    const int wid  = threadIdx.x >> 5;
    if (lane == 0) warp_sums[wid] = acc;
    __syncthreads();

    if (wid == 0) {
        double v = (lane < 8) ? warp_sums[lane] : 0.0;
        #pragma unroll
        for (int off = 4; off > 0; off >>= 1)
            v += __shfl_down_sync(0xFFFFFFFFu, v, off);
        if (lane == 0)
            atomicAdd(&g_fdloss_sum, v);
    }
}

__global__ void fdloss_finalize_kernel(float* __restrict__ out, double inv_n) {
    out[0] = (float)(g_fdloss_sum * inv_n);
}

extern "C" void kernel_launch(void* const* d_in, const int* in_sizes, int n_in,
                              void* d_out, int out_size) {
    const float* src = (const float*)d_in[0];  // source -> b
    const float* tgt = (const float*)d_in[1];  // target -> a
    float* out = (float*)d_out;

    const long long n = (long long)in_sizes[0];
    const long long n4 = n / 4;   // n = 51,380,224, divisible by 4

    fdloss_zero_kernel<<<1, 1>>>();

    const int threads = 256;
    int blocks = 148 * 8;  // full-chip occupancy with ~42 iters/thread
    long long max_blocks = (n4 + threads - 1) / threads;
    if ((long long)blocks > max_blocks) blocks = (int)max_blocks;

    fdloss_reduce_kernel<<<blocks, threads>>>(
        (const float4*)src, (const float4*)tgt, n4);

    fdloss_finalize_kernel<<<1, 1>>>(out, 1.0 / (double)n);
}

// round 3
// speedup vs baseline: 1.0169x; 1.0169x over previous
#include <cuda_runtime.h>
#include <cuda_bf16.h>

// Scalar reduction: mean over all elements of
//   term = (a<0 && b<0) ? (b - 2a)^2 : b^2
// where a = target (d_in[1]), b = source (d_in[0]).
// Derivation: fdback - a = (a<0&&b<0) ? (b-a)-a = b-2a : (a-b)-a = -b.
//
// Single-kernel design: per-block partial sums atomicAdd into a __device__
// accumulator; a wrapping ticket counter elects the last block, which writes
// the final mean to d_out and resets the accumulator to zero — so the kernel
// restores its own initial state and stays deterministic under graph replay.

__device__ double       g_fdloss_sum;    // zero-initialized at module load
__device__ unsigned int g_fdloss_tick;   // zero-initialized; self-wrapping

__global__ __launch_bounds__(256) void fdloss_kernel(
    const float4* __restrict__ src,   // b
    const float4* __restrict__ tgt,   // a
    long long n4,
    float* __restrict__ out,
    double inv_n)
{
    const long long stride = (long long)gridDim.x * blockDim.x;
    long long i = (long long)blockIdx.x * blockDim.x + threadIdx.x;

    double acc = 0.0;

    // 2-way ILP over float4 pairs; __ldcs = streaming (evict-first), no reuse
    for (; i + stride < n4; i += 2 * stride) {
        float4 b0 = __ldcs(&src[i]);
        float4 a0 = __ldcs(&tgt[i]);
        float4 b1 = __ldcs(&src[i + stride]);
        float4 a1 = __ldcs(&tgt[i + stride]);

        float s0, s1;
        {
            float t;
            t = (a0.x < 0.f && b0.x < 0.f) ? (b0.x - 2.f * a0.x) : b0.x;
            s0 = t * t;
            t = (a0.y < 0.f && b0.y < 0.f) ? (b0.y - 2.f * a0.y) : b0.y;
            s0 += t * t;
            t = (a0.z < 0.f && b0.z < 0.f) ? (b0.z - 2.f * a0.z) : b0.z;
            s0 += t * t;
            t = (a0.w < 0.f && b0.w < 0.f) ? (b0.w - 2.f * a0.w) : b0.w;
            s0 += t * t;
        }
        {
            float t;
            t = (a1.x < 0.f && b1.x < 0.f) ? (b1.x - 2.f * a1.x) : b1.x;
            s1 = t * t;
            t = (a1.y < 0.f && b1.y < 0.f) ? (b1.y - 2.f * a1.y) : b1.y;
            s1 += t * t;
            t = (a1.z < 0.f && b1.z < 0.f) ? (b1.z - 2.f * a1.z) : b1.z;
            s1 += t * t;
            t = (a1.w < 0.f && b1.w < 0.f) ? (b1.w - 2.f * a1.w) : b1.w;
            s1 += t * t;
        }
        acc += (double)s0 + (double)s1;
    }
    // tail (at most one float4 per thread)
    if (i < n4) {
        float4 b0 = __ldcs(&src[i]);
        float4 a0 = __ldcs(&tgt[i]);
        float t, s0;
        t = (a0.x < 0.f && b0.x < 0.f) ? (b0.x - 2.f * a0.x) : b0.x;
        s0 = t * t;
        t = (a0.y < 0.f && b0.y < 0.f) ? (b0.y - 2.f * a0.y) : b0.y;
        s0 += t * t;
        t = (a0.z < 0.f && b0.z < 0.f) ? (b0.z - 2.f * a0.z) : b0.z;
        s0 += t * t;
        t = (a0.w < 0.f && b0.w < 0.f) ? (b0.w - 2.f * a0.w) : b0.w;
        s0 += t * t;
        acc += (double)s0;
    }

    // warp reduce (double)
    #pragma unroll
    for (int off = 16; off > 0; off >>= 1)
        acc += __shfl_down_sync(0xFFFFFFFFu, acc, off);

    __shared__ double warp_sums[8];  // 256 threads = 8 warps
    const int lane = threadIdx.x & 31;
    const int wid  = threadIdx.x >> 5;
    if (lane == 0) warp_sums[wid] = acc;
    __syncthreads();

    __shared__ bool is_last;
    if (threadIdx.x == 0) {
        double v = warp_sums[0];
        #pragma unroll
        for (int w = 1; w < 8; w++) v += warp_sums[w];
        atomicAdd(&g_fdloss_sum, v);
        // ensure our atomicAdd is visible before the ticket increment
        __threadfence();
        // atomicInc wraps: when old == gridDim.x-1, new value = 0 (self-reset)
        unsigned int ticket = atomicInc(&g_fdloss_tick, gridDim.x - 1u);
        is_last = (ticket == gridDim.x - 1u);
    }
    __syncthreads();

    if (is_last && threadIdx.x == 0) {
        __threadfence();  // acquire: see all blocks' atomicAdds
        double s = g_fdloss_sum;
        out[0] = (float)(s * inv_n);
        g_fdloss_sum = 0.0;  // restore initial state for next graph replay
    }
}

extern "C" void kernel_launch(void* const* d_in, const int* in_sizes, int n_in,
                              void* d_out, int out_size) {
    const float* src = (const float*)d_in[0];  // source -> b
    const float* tgt = (const float*)d_in[1];  // target -> a
    float* out = (float*)d_out;

    const long long n = (long long)in_sizes[0];
    const long long n4 = n / 4;   // n = 51,380,224, divisible by 4

    const int threads = 256;
    long long max_blocks = (n4 + threads - 1) / threads;
    int blocks = 148 * 8;
    if ((long long)blocks > max_blocks) blocks = (int)max_blocks;
    if (blocks < 1) blocks = 1;

    fdloss_kernel<<<blocks, threads>>>(
        (const float4*)src, (const float4*)tgt, n4, out, 1.0 / (double)n);
}

// round 6
// speedup vs baseline: 1.0587x; 1.0411x over previous
#include <cuda_runtime.h>
#include <cuda_bf16.h>

// Scalar reduction: mean over all elements of
//   term = (a<0 && b<0) ? (b - 2a)^2 : b^2
// where a = target (d_in[1]), b = source (d_in[0]).
// Derivation: fdback - a = (a<0&&b<0) ? (b-a)-a = b-2a : (a-b)-a = -b.
//
// Single-kernel, self-resetting (graph-replay-safe) reduction:
// per-block partials atomicAdd into a __device__ double; wrapping ticket
// elects the last block, which writes the mean and restores the zero state.

__device__ double       g_fdloss_sum;    // zero-initialized at module load
__device__ unsigned int g_fdloss_tick;   // zero-initialized; self-wrapping

__global__ __launch_bounds__(256) void fdloss_kernel(
    const float4* __restrict__ src,   // b
    const float4* __restrict__ tgt,   // a
    int n4,
    float* __restrict__ out,
    double inv_n)
{
    const int stride = gridDim.x * blockDim.x;
    int i = blockIdx.x * blockDim.x + threadIdx.x;

    double acc = 0.0;

    // 2-way ILP over float4 pairs; default cache policy (LDG.E.128)
    for (; i + stride < n4; i += 2 * stride) {
        float4 b0 = src[i];
        float4 a0 = tgt[i];
        float4 b1 = src[i + stride];
        float4 a1 = tgt[i + stride];

        float s0, s1;
        {
            float t;
            t = (a0.x < 0.f && b0.x < 0.f) ? (b0.x - 2.f * a0.x) : b0.x;
            s0 = t * t;
            t = (a0.y < 0.f && b0.y < 0.f) ? (b0.y - 2.f * a0.y) : b0.y;
            s0 += t * t;
            t = (a0.z < 0.f && b0.z < 0.f) ? (b0.z - 2.f * a0.z) : b0.z;
            s0 += t * t;
            t = (a0.w < 0.f && b0.w < 0.f) ? (b0.w - 2.f * a0.w) : b0.w;
            s0 += t * t;
        }
        {
            float t;
            t = (a1.x < 0.f && b1.x < 0.f) ? (b1.x - 2.f * a1.x) : b1.x;
            s1 = t * t;
            t = (a1.y < 0.f && b1.y < 0.f) ? (b1.y - 2.f * a1.y) : b1.y;
            s1 += t * t;
            t = (a1.z < 0.f && b1.z < 0.f) ? (b1.z - 2.f * a1.z) : b1.z;
            s1 += t * t;
            t = (a1.w < 0.f && b1.w < 0.f) ? (b1.w - 2.f * a1.w) : b1.w;
            s1 += t * t;
        }
        acc += (double)s0 + (double)s1;
    }
    // tail (at most one float4 per thread)
    if (i < n4) {
        float4 b0 = src[i];
        float4 a0 = tgt[i];
        float t, s0;
        t = (a0.x < 0.f && b0.x < 0.f) ? (b0.x - 2.f * a0.x) : b0.x;
        s0 = t * t;
        t = (a0.y < 0.f && b0.y < 0.f) ? (b0.y - 2.f * a0.y) : b0.y;
        s0 += t * t;
        t = (a0.z < 0.f && b0.z < 0.f) ? (b0.z - 2.f * a0.z) : b0.z;
        s0 += t * t;
        t = (a0.w < 0.f && b0.w < 0.f) ? (b0.w - 2.f * a0.w) : b0.w;
        s0 += t * t;
        acc += (double)s0;
    }

    // warp reduce (double)
    #pragma unroll
    for (int off = 16; off > 0; off >>= 1)
        acc += __shfl_down_sync(0xFFFFFFFFu, acc, off);

    __shared__ double warp_sums[8];  // 256 threads = 8 warps
    const int lane = threadIdx.x & 31;
    const int wid  = threadIdx.x >> 5;
    if (lane == 0) warp_sums[wid] = acc;
    __syncthreads();

    __shared__ bool is_last;
    if (threadIdx.x == 0) {
        double v = warp_sums[0];
        #pragma unroll
        for (int w = 1; w < 8; w++) v += warp_sums[w];
        atomicAdd(&g_fdloss_sum, v);
        __threadfence();
        // atomicInc wraps: when old == gridDim.x-1, new value = 0 (self-reset)
        unsigned int ticket = atomicInc(&g_fdloss_tick, gridDim.x - 1u);
        is_last = (ticket == gridDim.x - 1u);
    }
    __syncthreads();

    if (is_last && threadIdx.x == 0) {
        __threadfence();  // see all blocks' atomicAdds
        double s = g_fdloss_sum;
        out[0] = (float)(s * inv_n);
        g_fdloss_sum = 0.0;  // restore initial state for next graph replay
    }
}

extern "C" void kernel_launch(void* const* d_in, const int* in_sizes, int n_in,
                              void* d_out, int out_size) {
    const float* src = (const float*)d_in[0];  // source -> b
    const float* tgt = (const float*)d_in[1];  // target -> a
    float* out = (float*)d_out;

    const long long n = (long long)in_sizes[0];
    const int n4 = (int)(n / 4);   // n = 51,380,224 -> n4 = 12,845,056 (fits int32)

    const int threads = 256;
    long long max_blocks = ((long long)n4 + threads - 1) / threads;
    int blocks = 148 * 8;
    if ((long long)blocks > max_blocks) blocks = (int)max_blocks;
    if (blocks < 1) blocks = 1;

    fdloss_kernel<<<blocks, threads>>>(
        (const float4*)src, (const float4*)tgt, n4, out, 1.0 / (double)n);
}